// round 1
// baseline (speedup 1.0000x reference)
#include <cuda_runtime.h>
#include <stdint.h>

#define K_CODES 1024
#define D_DIM   256
#define N_TOK   32768
#define S_PER_B 4096
#define Q_ELEMS (8u*256u*4096u)   /* 8388608 */

#define BM 128
#define BN 128
#define BK 16

// ---------------- device scratch (no allocations allowed) ----------------
__device__ float g_eTm2[D_DIM * K_CODES];   // -2 * embed^T, [D][K]
__device__ float g_e2[K_CODES];             // |e_k|^2
__device__ int   g_idx[N_TOK];
__device__ float g_batch_cs[K_CODES];
__device__ float g_dw[K_CODES * D_DIM];
__device__ float g_partials[64 * 128];
__device__ float g_cs[K_CODES];

// ---------------- prep: e2 + scaled transpose ----------------
__global__ void k_prep(const float* __restrict__ embed) {
    int k = blockIdx.x;
    int d = threadIdx.x;
    float v = embed[k * D_DIM + d];
    g_eTm2[d * K_CODES + k] = -2.0f * v;
    float s = v * v;
    #pragma unroll
    for (int o = 16; o; o >>= 1) s += __shfl_down_sync(0xffffffffu, s, o);
    __shared__ float ws[8];
    if ((d & 31) == 0) ws[d >> 5] = s;
    __syncthreads();
    if (d == 0) {
        float t = 0.f;
        #pragma unroll
        for (int i = 0; i < 8; i++) t += ws[i];
        g_e2[k] = t;
    }
}

// ---------------- main: fp32 GEMM + argmin epilogue ----------------
// score(n,k) = sum_d x[n,d] * (-2 e[k,d])  + |e_k|^2   (== d2 - |x|^2)
__global__ void __launch_bounds__(256, 2) k_argmin(
    const float* __restrict__ x, float* __restrict__ idxf_out)
{
    __shared__ __align__(16) float smem[4 * BK * BM];   // 32 KB
    float* sAbuf[2] = { smem,        smem + 2048 };
    float* sBbuf[2] = { smem + 4096, smem + 6144 };

    const int tid = threadIdx.x;
    const int tx  = tid & 15;
    const int ty  = tid >> 4;
    const int m0  = blockIdx.x * BM;
    const int b   = m0 >> 12;
    const int s0  = m0 & 4095;
    const float* Abase = x + (size_t)b * (D_DIM * S_PER_B) + s0;

    const int lr = tid >> 5;          // loader row 0..7
    const int lc = (tid & 31) << 2;   // loader col 0..124

    float minv[8];
    int   mini[8];
    #pragma unroll
    for (int i = 0; i < 8; i++) { minv[i] = 3.4e38f; mini[i] = 0; }

    for (int k0 = 0; k0 < K_CODES; k0 += BN) {
        float acc[8][8];
        #pragma unroll
        for (int i = 0; i < 8; i++)
            #pragma unroll
            for (int j = 0; j < 8; j++) acc[i][j] = 0.f;

        // prologue: load d-tile 0
        const float* ap = Abase + lr * S_PER_B + lc;
        const float* bp = g_eTm2 + lr * K_CODES + k0 + lc;
        float4 ra0 = *(const float4*)(ap);
        float4 ra1 = *(const float4*)(ap + 8 * S_PER_B);
        float4 rb0 = *(const float4*)(bp);
        float4 rb1 = *(const float4*)(bp + 8 * K_CODES);
        *(float4*)(sAbuf[0] + lr * BM + lc)        = ra0;
        *(float4*)(sAbuf[0] + (lr + 8) * BM + lc)  = ra1;
        *(float4*)(sBbuf[0] + lr * BN + lc)        = rb0;
        *(float4*)(sBbuf[0] + (lr + 8) * BN + lc)  = rb1;
        __syncthreads();

        int cur = 0;
        #pragma unroll 1
        for (int dt = 0; dt < 16; dt++) {
            if (dt < 15) {
                const float* ap2 = Abase + ((dt + 1) * BK + lr) * S_PER_B + lc;
                const float* bp2 = g_eTm2 + ((dt + 1) * BK + lr) * K_CODES + k0 + lc;
                ra0 = *(const float4*)(ap2);
                ra1 = *(const float4*)(ap2 + 8 * S_PER_B);
                rb0 = *(const float4*)(bp2);
                rb1 = *(const float4*)(bp2 + 8 * K_CODES);
            }
            const float* cA = sAbuf[cur];
            const float* cB = sBbuf[cur];
            #pragma unroll
            for (int kk = 0; kk < BK; kk++) {
                float4 A0 = *(const float4*)(cA + kk * BM + ty * 8);
                float4 A1 = *(const float4*)(cA + kk * BM + ty * 8 + 4);
                float4 B0 = *(const float4*)(cB + kk * BN + tx * 8);
                float4 B1 = *(const float4*)(cB + kk * BN + tx * 8 + 4);
                float a[8]  = {A0.x, A0.y, A0.z, A0.w, A1.x, A1.y, A1.z, A1.w};
                float bb[8] = {B0.x, B0.y, B0.z, B0.w, B1.x, B1.y, B1.z, B1.w};
                #pragma unroll
                for (int i = 0; i < 8; i++)
                    #pragma unroll
                    for (int j = 0; j < 8; j++)
                        acc[i][j] = fmaf(a[i], bb[j], acc[i][j]);
            }
            if (dt < 15) {
                int nxt = cur ^ 1;
                *(float4*)(sAbuf[nxt] + lr * BM + lc)       = ra0;
                *(float4*)(sAbuf[nxt] + (lr + 8) * BM + lc) = ra1;
                *(float4*)(sBbuf[nxt] + lr * BN + lc)       = rb0;
                *(float4*)(sBbuf[nxt] + (lr + 8) * BN + lc) = rb1;
                __syncthreads();
                cur = nxt;
            }
        }

        // epilogue: add |e|^2, update running argmin
        float4 E0 = *(const float4*)(g_e2 + k0 + tx * 8);
        float4 E1 = *(const float4*)(g_e2 + k0 + tx * 8 + 4);
        float ev[8] = {E0.x, E0.y, E0.z, E0.w, E1.x, E1.y, E1.z, E1.w};
        #pragma unroll
        for (int i = 0; i < 8; i++)
            #pragma unroll
            for (int j = 0; j < 8; j++) {
                float v = acc[i][j] + ev[j];
                if (v < minv[i]) { minv[i] = v; mini[i] = k0 + tx * 8 + j; }
            }
        __syncthreads();   // before next k-tile reuses smem buffers
    }

    // cross-thread reduction: 16 threads (tx) share each of 128 rows
    float* redv = smem;                    // [128][16]
    int*   redi = (int*)(smem + 2048);     // [128][16]
    #pragma unroll
    for (int i = 0; i < 8; i++) {
        int row = ty * 8 + i;
        redv[row * 16 + tx] = minv[i];
        redi[row * 16 + tx] = mini[i];
    }
    __syncthreads();
    if (tid < BM) {
        float bv = redv[tid * 16];
        int   bi = redi[tid * 16];
        #pragma unroll
        for (int q = 1; q < 16; q++) {
            float v = redv[tid * 16 + q];
            int  ii = redi[tid * 16 + q];
            if (v < bv || (v == bv && ii < bi)) { bv = v; bi = ii; }
        }
        int n = m0 + tid;
        g_idx[n] = bi;
        idxf_out[n] = (float)bi;
        atomicAdd(&g_batch_cs[bi], 1.0f);
    }
}

// ---------------- dw scatter: vectorized global reductions ----------------
__global__ void k_dw(const float* __restrict__ x) {
    int d0 = blockIdx.x << 2;
    int n  = (blockIdx.y << 8) + threadIdx.x;
    int b = n >> 12, s = n & 4095;
    const float* p = x + (size_t)b * (D_DIM * S_PER_B) + s;
    float v0 = p[(size_t)(d0 + 0) * S_PER_B];
    float v1 = p[(size_t)(d0 + 1) * S_PER_B];
    float v2 = p[(size_t)(d0 + 2) * S_PER_B];
    float v3 = p[(size_t)(d0 + 3) * S_PER_B];
    float* dst = g_dw + g_idx[n] * D_DIM + d0;
    asm volatile("red.global.add.v4.f32 [%0], {%1,%2,%3,%4};"
                 :: "l"(dst), "f"(v0), "f"(v1), "f"(v2), "f"(v3) : "memory");
}

// ---------------- quantized gather/write + loss partials ----------------
__global__ void k_quant(const float* __restrict__ x,
                        const float* __restrict__ embed,
                        float* __restrict__ qout)
{
    int d0 = blockIdx.x << 2;
    int n  = (blockIdx.y << 8) + threadIdx.x;
    int b = n >> 12, s = n & 4095;
    size_t base = (size_t)b * (D_DIM * S_PER_B) + s;
    int k = g_idx[n];
    float4 q = *(const float4*)(embed + k * D_DIM + d0);
    float ls = 0.f, xv, t;
    xv = x[base + (size_t)(d0 + 0) * S_PER_B]; t = q.x - xv; qout[base + (size_t)(d0 + 0) * S_PER_B] = xv + t; ls += t * t;
    xv = x[base + (size_t)(d0 + 1) * S_PER_B]; t = q.y - xv; qout[base + (size_t)(d0 + 1) * S_PER_B] = xv + t; ls += t * t;
    xv = x[base + (size_t)(d0 + 2) * S_PER_B]; t = q.z - xv; qout[base + (size_t)(d0 + 2) * S_PER_B] = xv + t; ls += t * t;
    xv = x[base + (size_t)(d0 + 3) * S_PER_B]; t = q.w - xv; qout[base + (size_t)(d0 + 3) * S_PER_B] = xv + t; ls += t * t;

    #pragma unroll
    for (int o = 16; o; o >>= 1) ls += __shfl_down_sync(0xffffffffu, ls, o);
    __shared__ float ws[8];
    int tid = threadIdx.x;
    if ((tid & 31) == 0) ws[tid >> 5] = ls;
    __syncthreads();
    if (tid == 0) {
        float sum = 0.f;
        #pragma unroll
        for (int i = 0; i < 8; i++) sum += ws[i];
        g_partials[blockIdx.y * 64 + blockIdx.x] = sum;
    }
}

// ---------------- finalize: loss, cluster-size normalization ----------------
__global__ void k_final(const float* __restrict__ cluster_size,
                        float* __restrict__ loss_out)
{
    __shared__ float sb[1024];
    int t = threadIdx.x;
    float s = 0.f;
    for (int i = t; i < 64 * 128; i += 1024) s += g_partials[i];
    sb[t] = s; __syncthreads();
    for (int o = 512; o; o >>= 1) { if (t < o) sb[t] += sb[t + o]; __syncthreads(); }
    if (t == 0) loss_out[0] = 0.25f * sb[0] / (float)Q_ELEMS;
    __syncthreads();

    float ncs = cluster_size[t] * 0.99f + 0.01f * g_batch_cs[t];
    sb[t] = ncs; __syncthreads();
    for (int o = 512; o; o >>= 1) { if (t < o) sb[t] += sb[t + o]; __syncthreads(); }
    float nsum = sb[0];
    g_cs[t] = nsum * (ncs + 1e-5f) / (nsum + 1024.0f * 1e-5f);
}

// ---------------- new embed ----------------
__global__ void k_newembed(const float* __restrict__ embed_avg,
                           float* __restrict__ out)
{
    int k = blockIdx.x, d = threadIdx.x;
    int o = k * D_DIM + d;
    out[o] = (embed_avg[o] * 0.99f + 0.01f * g_dw[o]) / g_cs[k];
}

// ---------------- launch ----------------
extern "C" void kernel_launch(void* const* d_in, const int* in_sizes, int n_in,
                              void* d_out, int out_size)
{
    const float* x          = (const float*)d_in[0];
    const float* embed      = (const float*)d_in[1];
    const float* embed_avg  = (const float*)d_in[2];
    const float* cluster    = (const float*)d_in[3];

    float* out     = (float*)d_out;
    float* out_q   = out + 1;                 // quantized [B,C,T,H,W]
    float* out_idx = out_q + Q_ELEMS;         // idx as float [B,T,H,W]
    float* out_e   = out_idx + N_TOK;         // new_embed [K,D]

    void *p_dw, *p_bc;
    cudaGetSymbolAddress(&p_dw, g_dw);
    cudaGetSymbolAddress(&p_bc, g_batch_cs);
    cudaMemsetAsync(p_dw, 0, sizeof(float) * K_CODES * D_DIM, 0);
    cudaMemsetAsync(p_bc, 0, sizeof(float) * K_CODES, 0);

    k_prep<<<K_CODES, D_DIM>>>(embed);
    k_argmin<<<N_TOK / BM, 256>>>(x, out_idx);
    dim3 g(64, 128);
    k_dw<<<g, 256>>>(x);
    k_quant<<<g, 256>>>(x, embed, out_q);
    k_final<<<1, 1024>>>(cluster, out);
    k_newembed<<<K_CODES, D_DIM>>>(embed_avg, out_e);
}

// round 2
// speedup vs baseline: 1.1300x; 1.1300x over previous
#include <cuda_runtime.h>
#include <stdint.h>

#define K_CODES 1024
#define D_DIM   256
#define N_TOK   32768
#define S_PER_B 4096
#define Q_ELEMS (8u*256u*4096u)   /* 8388608 */

#define BM 128
#define BN 128
#define BK 16

// ---------------- device scratch (no allocations allowed) ----------------
__device__ float g_eTm2[D_DIM * K_CODES];   // -2 * embed^T, [D][K]
__device__ float g_e2[K_CODES];             // |e_k|^2
__device__ int   g_idx[N_TOK];
__device__ float g_batch_cs[K_CODES];
__device__ float g_dw[K_CODES * D_DIM];
__device__ float g_partials[64 * 128];
__device__ float g_cs[K_CODES];

// ---------------- prep: e2 + scaled transpose ----------------
__global__ void k_prep(const float* __restrict__ embed) {
    int k = blockIdx.x;
    int d = threadIdx.x;
    float v = embed[k * D_DIM + d];
    g_eTm2[d * K_CODES + k] = -2.0f * v;
    float s = v * v;
    #pragma unroll
    for (int o = 16; o; o >>= 1) s += __shfl_down_sync(0xffffffffu, s, o);
    __shared__ float ws[8];
    if ((d & 31) == 0) ws[d >> 5] = s;
    __syncthreads();
    if (d == 0) {
        float t = 0.f;
        #pragma unroll
        for (int i = 0; i < 8; i++) t += ws[i];
        g_e2[k] = t;
    }
}

// ---------------- main: fp32x2 packed GEMM + argmin epilogue ----------------
// score(n,k) = sum_d x[n,d] * (-2 e[k,d])  + |e_k|^2   (== d2 - |x|^2)
// Accumulators packed along the j (codebook) axis as f32x2 pairs; B pairs come
// free from the 16B smem loads; A scalar is broadcast-packed via mov.b64.
// Per-element fma order is identical to the scalar version (bitwise same).
__global__ void __launch_bounds__(256, 2) k_argmin(
    const float* __restrict__ x, float* __restrict__ idxf_out)
{
    __shared__ __align__(16) float smem[4 * BK * BM];   // 32 KB
    float* sAbuf[2] = { smem,        smem + 2048 };
    float* sBbuf[2] = { smem + 4096, smem + 6144 };

    const int tid = threadIdx.x;
    const int tx  = tid & 15;
    const int ty  = tid >> 4;
    const int m0  = blockIdx.x * BM;
    const int b   = m0 >> 12;
    const int s0  = m0 & 4095;
    const float* Abase = x + (size_t)b * (D_DIM * S_PER_B) + s0;

    const int lr = tid >> 5;          // loader row 0..7
    const int lc = (tid & 31) << 2;   // loader col 0..124

    float minv[8];
    int   mini[8];
    #pragma unroll
    for (int i = 0; i < 8; i++) { minv[i] = 3.4e38f; mini[i] = 0; }

    for (int k0 = 0; k0 < K_CODES; k0 += BN) {
        // acc2[i][jp] = (acc[i][2jp], acc[i][2jp+1]) packed f32x2
        unsigned long long acc2[8][4];
        #pragma unroll
        for (int i = 0; i < 8; i++)
            #pragma unroll
            for (int j = 0; j < 4; j++) acc2[i][j] = 0ull;

        // prologue: load d-tile 0
        const float* ap = Abase + lr * S_PER_B + lc;
        const float* bp = g_eTm2 + lr * K_CODES + k0 + lc;
        float4 ra0 = *(const float4*)(ap);
        float4 ra1 = *(const float4*)(ap + 8 * S_PER_B);
        float4 rb0 = *(const float4*)(bp);
        float4 rb1 = *(const float4*)(bp + 8 * K_CODES);
        *(float4*)(sAbuf[0] + lr * BM + lc)        = ra0;
        *(float4*)(sAbuf[0] + (lr + 8) * BM + lc)  = ra1;
        *(float4*)(sBbuf[0] + lr * BN + lc)        = rb0;
        *(float4*)(sBbuf[0] + (lr + 8) * BN + lc)  = rb1;
        __syncthreads();

        int cur = 0;
        #pragma unroll 1
        for (int dt = 0; dt < 16; dt++) {
            if (dt < 15) {
                const float* ap2 = Abase + ((dt + 1) * BK + lr) * S_PER_B + lc;
                const float* bp2 = g_eTm2 + ((dt + 1) * BK + lr) * K_CODES + k0 + lc;
                ra0 = *(const float4*)(ap2);
                ra1 = *(const float4*)(ap2 + 8 * S_PER_B);
                rb0 = *(const float4*)(bp2);
                rb1 = *(const float4*)(bp2 + 8 * K_CODES);
            }
            const float* cA = sAbuf[cur];
            const float* cB = sBbuf[cur];
            #pragma unroll
            for (int kk = 0; kk < BK; kk++) {
                float4 A0 = *(const float4*)(cA + kk * BM + ty * 8);
                float4 A1 = *(const float4*)(cA + kk * BM + ty * 8 + 4);
                // B pairs directly as packed f32x2 (16B-aligned smem)
                ulonglong2 Bp0 = *(const ulonglong2*)(cB + kk * BN + tx * 8);
                ulonglong2 Bp1 = *(const ulonglong2*)(cB + kk * BN + tx * 8 + 4);
                unsigned long long b2[4] = {Bp0.x, Bp0.y, Bp1.x, Bp1.y};
                float a[8] = {A0.x, A0.y, A0.z, A0.w, A1.x, A1.y, A1.z, A1.w};
                #pragma unroll
                for (int i = 0; i < 8; i++) {
                    unsigned long long a2;
                    asm("mov.b64 %0, {%1, %1};" : "=l"(a2) : "f"(a[i]));
                    #pragma unroll
                    for (int j = 0; j < 4; j++)
                        asm("fma.rn.f32x2 %0, %1, %2, %0;"
                            : "+l"(acc2[i][j]) : "l"(a2), "l"(b2[j]));
                }
            }
            if (dt < 15) {
                int nxt = cur ^ 1;
                *(float4*)(sAbuf[nxt] + lr * BM + lc)       = ra0;
                *(float4*)(sAbuf[nxt] + (lr + 8) * BM + lc) = ra1;
                *(float4*)(sBbuf[nxt] + lr * BN + lc)       = rb0;
                *(float4*)(sBbuf[nxt] + (lr + 8) * BN + lc) = rb1;
                __syncthreads();
                cur = nxt;
            }
        }

        // epilogue: add |e|^2, update running argmin
        float4 E0 = *(const float4*)(g_e2 + k0 + tx * 8);
        float4 E1 = *(const float4*)(g_e2 + k0 + tx * 8 + 4);
        float ev[8] = {E0.x, E0.y, E0.z, E0.w, E1.x, E1.y, E1.z, E1.w};
        #pragma unroll
        for (int i = 0; i < 8; i++) {
            #pragma unroll
            for (int jp = 0; jp < 4; jp++) {
                unsigned lo, hi;
                asm("mov.b64 {%0, %1}, %2;" : "=r"(lo), "=r"(hi) : "l"(acc2[i][jp]));
                float v0 = __uint_as_float(lo) + ev[2 * jp];
                float v1 = __uint_as_float(hi) + ev[2 * jp + 1];
                int j0 = k0 + tx * 8 + 2 * jp;
                if (v0 < minv[i]) { minv[i] = v0; mini[i] = j0; }
                if (v1 < minv[i]) { minv[i] = v1; mini[i] = j0 + 1; }
            }
        }
        __syncthreads();   // before next k-tile reuses smem buffers
    }

    // cross-thread reduction: 16 threads (tx) share each of 128 rows
    float* redv = smem;                    // [128][16]
    int*   redi = (int*)(smem + 2048);     // [128][16]
    #pragma unroll
    for (int i = 0; i < 8; i++) {
        int row = ty * 8 + i;
        redv[row * 16 + tx] = minv[i];
        redi[row * 16 + tx] = mini[i];
    }
    __syncthreads();
    if (tid < BM) {
        float bv = redv[tid * 16];
        int   bi = redi[tid * 16];
        #pragma unroll
        for (int q = 1; q < 16; q++) {
            float v = redv[tid * 16 + q];
            int  ii = redi[tid * 16 + q];
            if (v < bv || (v == bv && ii < bi)) { bv = v; bi = ii; }
        }
        int n = m0 + tid;
        g_idx[n] = bi;
        idxf_out[n] = (float)bi;
        atomicAdd(&g_batch_cs[bi], 1.0f);
    }
}

// ---------------- fused quantized write + loss partials + dw scatter ----------------
__global__ void k_quant_dw(const float* __restrict__ x,
                           const float* __restrict__ embed,
                           float* __restrict__ qout)
{
    int d0 = blockIdx.x << 2;
    int n  = (blockIdx.y << 8) + threadIdx.x;
    int b = n >> 12, s = n & 4095;
    size_t base = (size_t)b * (D_DIM * S_PER_B) + s;
    int k = g_idx[n];
    float4 q = *(const float4*)(embed + k * D_DIM + d0);

    float x0 = x[base + (size_t)(d0 + 0) * S_PER_B];
    float x1 = x[base + (size_t)(d0 + 1) * S_PER_B];
    float x2 = x[base + (size_t)(d0 + 2) * S_PER_B];
    float x3 = x[base + (size_t)(d0 + 3) * S_PER_B];

    float t0 = q.x - x0, t1 = q.y - x1, t2 = q.z - x2, t3 = q.w - x3;
    qout[base + (size_t)(d0 + 0) * S_PER_B] = x0 + t0;
    qout[base + (size_t)(d0 + 1) * S_PER_B] = x1 + t1;
    qout[base + (size_t)(d0 + 2) * S_PER_B] = x2 + t2;
    qout[base + (size_t)(d0 + 3) * S_PER_B] = x3 + t3;
    float ls = t0 * t0 + t1 * t1 + t2 * t2 + t3 * t3;

    // dw scatter-add (same x values, saves a full second read of x)
    float* dst = g_dw + k * D_DIM + d0;
    asm volatile("red.global.add.v4.f32 [%0], {%1,%2,%3,%4};"
                 :: "l"(dst), "f"(x0), "f"(x1), "f"(x2), "f"(x3) : "memory");

    #pragma unroll
    for (int o = 16; o; o >>= 1) ls += __shfl_down_sync(0xffffffffu, ls, o);
    __shared__ float ws[8];
    int tid = threadIdx.x;
    if ((tid & 31) == 0) ws[tid >> 5] = ls;
    __syncthreads();
    if (tid == 0) {
        float sum = 0.f;
        #pragma unroll
        for (int i = 0; i < 8; i++) sum += ws[i];
        g_partials[blockIdx.y * 64 + blockIdx.x] = sum;
    }
}

// ---------------- finalize: loss, cluster-size normalization ----------------
__global__ void k_final(const float* __restrict__ cluster_size,
                        float* __restrict__ loss_out)
{
    __shared__ float sb[1024];
    int t = threadIdx.x;
    float s = 0.f;
    for (int i = t; i < 64 * 128; i += 1024) s += g_partials[i];
    sb[t] = s; __syncthreads();
    for (int o = 512; o; o >>= 1) { if (t < o) sb[t] += sb[t + o]; __syncthreads(); }
    if (t == 0) loss_out[0] = 0.25f * sb[0] / (float)Q_ELEMS;
    __syncthreads();

    float ncs = cluster_size[t] * 0.99f + 0.01f * g_batch_cs[t];
    sb[t] = ncs; __syncthreads();
    for (int o = 512; o; o >>= 1) { if (t < o) sb[t] += sb[t + o]; __syncthreads(); }
    float nsum = sb[0];
    g_cs[t] = nsum * (ncs + 1e-5f) / (nsum + 1024.0f * 1e-5f);
}

// ---------------- new embed ----------------
__global__ void k_newembed(const float* __restrict__ embed_avg,
                           float* __restrict__ out)
{
    int k = blockIdx.x, d = threadIdx.x;
    int o = k * D_DIM + d;
    out[o] = (embed_avg[o] * 0.99f + 0.01f * g_dw[o]) / g_cs[k];
}

// ---------------- launch ----------------
extern "C" void kernel_launch(void* const* d_in, const int* in_sizes, int n_in,
                              void* d_out, int out_size)
{
    const float* x          = (const float*)d_in[0];
    const float* embed      = (const float*)d_in[1];
    const float* embed_avg  = (const float*)d_in[2];
    const float* cluster    = (const float*)d_in[3];

    float* out     = (float*)d_out;
    float* out_q   = out + 1;                 // quantized [B,C,T,H,W]
    float* out_idx = out_q + Q_ELEMS;         // idx as float [B,T,H,W]
    float* out_e   = out_idx + N_TOK;         // new_embed [K,D]

    void *p_dw, *p_bc;
    cudaGetSymbolAddress(&p_dw, g_dw);
    cudaGetSymbolAddress(&p_bc, g_batch_cs);
    cudaMemsetAsync(p_dw, 0, sizeof(float) * K_CODES * D_DIM, 0);
    cudaMemsetAsync(p_bc, 0, sizeof(float) * K_CODES, 0);

    k_prep<<<K_CODES, D_DIM>>>(embed);
    k_argmin<<<N_TOK / BM, 256>>>(x, out_idx);
    dim3 g(64, 128);
    k_quant_dw<<<g, 256>>>(x, embed, out_q);
    k_final<<<1, 1024>>>(cluster, out);
    k_newembed<<<K_CODES, D_DIM>>>(embed_avg, out_e);
}